// round 1
// baseline (speedup 1.0000x reference)
#include <cuda_runtime.h>

// YOLO decode, all 3 scales fused into one launch.
// out layout (rows of 5 floats): scale13 rows [0, 32*169*3), then scale26, then scale52.
// row within scale = cell*3 + anchor, cell = b*H*W + h*W + w.

__global__ void detector_decode_kernel(const float* __restrict__ in13,
                                       const float* __restrict__ in26,
                                       const float* __restrict__ in52,
                                       const float* __restrict__ pthresh,
                                       float* __restrict__ out)
{
    const int HW13 = 13 * 13;   // 169
    const int HW26 = 26 * 26;   // 676
    const int HW52 = 52 * 52;   // 2704
    const int N13 = 32 * HW13;  // 5408 cells
    const int N26 = 32 * HW26;  // 21632
    const int N52 = 32 * HW52;  // 86528
    const int NTOT = N13 + N26 + N52;

    int i = blockIdx.x * blockDim.x + threadIdx.x;
    if (i >= NTOT) return;

    const float thresh = *pthresh;

    const float* __restrict__ in;
    int HW, W;
    float t;
    int c;            // cell index within scale
    long outBase;     // float offset of this scale's output block
    float aw0, aw1, aw2, ah0, ah1, ah2;

    if (i < N13) {
        in = in13; HW = HW13; W = 13; t = 32.0f; c = i; outBase = 0;
        aw0 = 116.0f; aw1 = 156.0f; aw2 = 373.0f;
        ah0 =  90.0f; ah1 = 198.0f; ah2 = 326.0f;
    } else if (i < N13 + N26) {
        in = in26; HW = HW26; W = 26; t = 16.0f; c = i - N13;
        outBase = (long)N13 * 15;
        aw0 = 30.0f; aw1 = 62.0f; aw2 = 59.0f;
        ah0 = 61.0f; ah1 = 45.0f; ah2 = 119.0f;
    } else {
        in = in52; HW = HW52; W = 52; t = 8.0f; c = i - N13 - N26;
        outBase = (long)(N13 + N26) * 15;
        aw0 = 10.0f; aw1 = 16.0f; aw2 = 33.0f;
        ah0 = 13.0f; ah1 = 30.0f; ah2 = 23.0f;
    }

    const int b  = c / HW;
    const int hw = c - b * HW;
    const int h  = hw / W;
    const int w  = hw - h * W;

    // input element for (b, channel ch, h, w) = b*255*HW + ch*HW + hw
    const float* __restrict__ base = in + (long)b * 255 * HW + hw;
    float* __restrict__ o = out + outBase + (long)c * 15;

    const float fb = (float)b;
    const float fw = (float)w;
    const float fh = (float)h;
    const float aws[3] = {aw0, aw1, aw2};
    const float ahs[3] = {ah0, ah1, ah2};

    #pragma unroll
    for (int a = 0; a < 3; ++a) {
        const float* __restrict__ p = base + (long)(a * 85) * HW;
        const float conf = p[0];
        if (conf > thresh) {
            const float tx = p[HW];
            const float ty = p[2 * HW];
            const float tw = p[3 * HW];
            const float th = p[4 * HW];
            o[a * 5 + 0] = fb;
            o[a * 5 + 1] = (fw + tx) * t;
            o[a * 5 + 2] = (fh + ty) * t;
            o[a * 5 + 3] = aws[a] * __expf(tw);
            o[a * 5 + 4] = ahs[a] * __expf(th);
        } else {
            o[a * 5 + 0] = 0.0f;
            o[a * 5 + 1] = 0.0f;
            o[a * 5 + 2] = 0.0f;
            o[a * 5 + 3] = 0.0f;
            o[a * 5 + 4] = 0.0f;
        }
    }
}

extern "C" void kernel_launch(void* const* d_in, const int* in_sizes, int n_in,
                              void* d_out, int out_size)
{
    const float* in13 = (const float*)d_in[0];
    const float* in26 = (const float*)d_in[1];
    const float* in52 = (const float*)d_in[2];
    const float* pthresh = (const float*)d_in[3];
    float* out = (float*)d_out;

    const int NTOT = 32 * (169 + 676 + 2704);  // 113568 cells
    const int threads = 256;
    const int blocks = (NTOT + threads - 1) / threads;
    detector_decode_kernel<<<blocks, threads>>>(in13, in26, in52, pthresh, out);
}

// round 2
// speedup vs baseline: 1.9183x; 1.9183x over previous
#include <cuda_runtime.h>

// YOLO decode, 3 scales fused, shared-memory staged coalesced output.
// out rows of 5 floats: scale13 [0, 5408*3), scale26, scale52.
// row within scale = cell*3 + anchor, cell = b*H*W + h*W + w.

#define TPB 256

__global__ __launch_bounds__(TPB) void detector_decode_kernel(
    const float* __restrict__ in13,
    const float* __restrict__ in26,
    const float* __restrict__ in52,
    const float* __restrict__ pthresh,
    float* __restrict__ out)
{
    __shared__ float s[TPB * 15];

    const int HW13 = 169, HW26 = 676, HW52 = 2704;
    const int N13 = 32 * HW13;   // 5408
    const int N26 = 32 * HW26;   // 21632
    const int N52 = 32 * HW52;   // 86528
    const int B13 = (N13 + TPB - 1) / TPB;   // 22
    const int B26 = (N26 + TPB - 1) / TPB;   // 85

    const int blk = blockIdx.x;
    const int tid = threadIdx.x;

    const float* __restrict__ in;
    int HW, W, N, cellBase;
    long outBase;
    float t;
    float aw0, aw1, aw2, ah0, ah1, ah2;

    if (blk < B13) {
        in = in13; HW = HW13; W = 13; t = 32.0f; N = N13;
        cellBase = blk * TPB; outBase = 0;
        aw0 = 116.0f; aw1 = 156.0f; aw2 = 373.0f;
        ah0 =  90.0f; ah1 = 198.0f; ah2 = 326.0f;
    } else if (blk < B13 + B26) {
        in = in26; HW = HW26; W = 26; t = 16.0f; N = N26;
        cellBase = (blk - B13) * TPB; outBase = (long)N13 * 15;
        aw0 = 30.0f; aw1 = 62.0f; aw2 = 59.0f;
        ah0 = 61.0f; ah1 = 45.0f; ah2 = 119.0f;
    } else {
        in = in52; HW = HW52; W = 52; t = 8.0f; N = N52;
        cellBase = (blk - B13 - B26) * TPB; outBase = (long)(N13 + N26) * 15;
        aw0 = 10.0f; aw1 = 16.0f; aw2 = 33.0f;
        ah0 = 13.0f; ah1 = 30.0f; ah2 = 23.0f;
    }

    const float thresh = __ldg(pthresh);
    const int c = cellBase + tid;

    if (c < N) {
        const int b  = c / HW;
        const int hw = c - b * HW;
        const int h  = hw / W;
        const int w  = hw - h * W;

        const float* __restrict__ base = in + (long)b * 255 * HW + hw;
        const float* __restrict__ p0 = base;
        const float* __restrict__ p1 = base + (long)85  * HW;
        const float* __restrict__ p2 = base + (long)170 * HW;

        // Front-batch ALL loads: 15 independent LDGs in flight.
        const float c0 = p0[0];
        const float x0 = p0[HW],     y0 = p0[2*HW], w0 = p0[3*HW], h0 = p0[4*HW];
        const float c1 = p1[0];
        const float x1 = p1[HW],     y1 = p1[2*HW], w1 = p1[3*HW], h1 = p1[4*HW];
        const float c2 = p2[0];
        const float x2 = p2[HW],     y2 = p2[2*HW], w2 = p2[3*HW], h2 = p2[4*HW];

        const float fb = (float)b;
        const float fw = (float)w;
        const float fh = (float)h;

        float* __restrict__ so = s + tid * 15;

        const bool m0 = c0 > thresh;
        so[0]  = m0 ? fb : 0.0f;
        so[1]  = m0 ? (fw + x0) * t : 0.0f;
        so[2]  = m0 ? (fh + y0) * t : 0.0f;
        so[3]  = m0 ? aw0 * __expf(w0) : 0.0f;
        so[4]  = m0 ? ah0 * __expf(h0) : 0.0f;

        const bool m1 = c1 > thresh;
        so[5]  = m1 ? fb : 0.0f;
        so[6]  = m1 ? (fw + x1) * t : 0.0f;
        so[7]  = m1 ? (fh + y1) * t : 0.0f;
        so[8]  = m1 ? aw1 * __expf(w1) : 0.0f;
        so[9]  = m1 ? ah1 * __expf(h1) : 0.0f;

        const bool m2 = c2 > thresh;
        so[10] = m2 ? fb : 0.0f;
        so[11] = m2 ? (fw + x2) * t : 0.0f;
        so[12] = m2 ? (fh + y2) * t : 0.0f;
        so[13] = m2 ? aw2 * __expf(w2) : 0.0f;
        so[14] = m2 ? ah2 * __expf(h2) : 0.0f;
    }

    __syncthreads();

    // Coalesced block write. All scale bases and valid counts are multiples
    // of 4 floats, so the float4 path is always aligned & exact.
    const int nvalid = min(TPB, N - cellBase);
    const int totFloats = nvalid * 15;
    float* __restrict__ dst = out + outBase + (long)cellBase * 15;

    if ((totFloats & 3) == 0) {
        float4* __restrict__ d4 = (float4*)dst;
        const float4* __restrict__ s4 = (const float4*)s;
        const int n4 = totFloats >> 2;
        #pragma unroll
        for (int i = tid; i < n4; i += TPB) d4[i] = s4[i];
    } else {
        for (int i = tid; i < totFloats; i += TPB) dst[i] = s[i];
    }
}

extern "C" void kernel_launch(void* const* d_in, const int* in_sizes, int n_in,
                              void* d_out, int out_size)
{
    const float* in13 = (const float*)d_in[0];
    const float* in26 = (const float*)d_in[1];
    const float* in52 = (const float*)d_in[2];
    const float* pthresh = (const float*)d_in[3];
    float* out = (float*)d_out;

    const int N13 = 32 * 169, N26 = 32 * 676, N52 = 32 * 2704;
    const int B13 = (N13 + TPB - 1) / TPB;   // 22
    const int B26 = (N26 + TPB - 1) / TPB;   // 85
    const int B52 = (N52 + TPB - 1) / TPB;   // 338
    detector_decode_kernel<<<B13 + B26 + B52, TPB>>>(in13, in26, in52, pthresh, out);
}